// round 1
// baseline (speedup 1.0000x reference)
#include <cuda_runtime.h>
#include <math.h>

#define NNODE 1000
#define NEDGE 16000
#define BATCH 32
#define TSTEP 64
#define CIN   8
#define HGC   16
#define HL    256
#define NOUTD 24
#define KDIM  8000          // N*C
#define JDIM  1024          // 4*HL
#define WIHK  16000         // N*HG

// ---------------- scratch (device globals; no allocation) ----------------
__device__ __align__(16) float g_Vraw[JDIM * KDIM];      // 32.8 MB
__device__ __align__(16) float g_V0[JDIM * KDIM];        // 32.8 MB
__device__ __align__(16) float g_gates[TSTEP * BATCH * JDIM]; // 8.4 MB
__device__ float g_biasfull[JDIM];
__device__ float g_deginv[NNODE];
__device__ float g_dis[NNODE];
__device__ float g_norm[NEDGE];
__device__ int   g_rowcnt[NNODE + 1];
__device__ int   g_rowptr[NNODE + 1];
__device__ int   g_cursor[NNODE];
__device__ int   g_erow[NEDGE];          // edge ids grouped by row
__device__ __align__(16) float g_h[2][BATCH * HL];
__device__ __align__(16) float g_c[2][BATCH * HL];

// ---------------- small prep kernels ----------------
__global__ void k_init() {
    int i = blockIdx.x * blockDim.x + threadIdx.x;
    if (i < NNODE) { g_deginv[i] = 1.0f; g_cursor[i] = 0; }
    if (i <= NNODE) g_rowcnt[i] = 0;
}

__global__ void k_deg_accum(const int* __restrict__ ei, const float* __restrict__ ew) {
    int e = blockIdx.x * blockDim.x + threadIdx.x;
    if (e < NEDGE) atomicAdd(&g_deginv[ei[NEDGE + e]], ew[e]); // col
}

__global__ void k_deg_finish() {
    int n = blockIdx.x * blockDim.x + threadIdx.x;
    if (n < NNODE) {
        float d = g_deginv[n];
        g_deginv[n] = 1.0f / d;
        g_dis[n] = rsqrtf(d);
    }
}

// norm per edge + row histogram
__global__ void k_norm_rowcnt(const int* __restrict__ ei, const float* __restrict__ ew) {
    int e = blockIdx.x * blockDim.x + threadIdx.x;
    if (e < NEDGE) {
        int r = ei[e], c = ei[NEDGE + e];
        g_norm[e] = g_dis[r] * ew[e] * g_dis[c];
        atomicAdd(&g_rowcnt[r], 1);
    }
}

// single-block exclusive scan of 1000 counts
__global__ void k_scan() {
    __shared__ int s[1024];
    int tid = threadIdx.x;
    int c = (tid < NNODE) ? g_rowcnt[tid] : 0;
    s[tid] = c;
    for (int off = 1; off < 1024; off <<= 1) {
        __syncthreads();
        int v = (tid >= off) ? s[tid - off] : 0;
        __syncthreads();
        s[tid] += v;
    }
    __syncthreads();
    if (tid < NNODE) {
        int ex = s[tid] - c;
        g_rowptr[tid] = ex;
        g_cursor[tid] = ex;
    }
    if (tid == 1023) g_rowptr[NNODE] = s[1023];
}

__global__ void k_scatter(const int* __restrict__ ei) {
    int e = blockIdx.x * blockDim.x + threadIdx.x;
    if (e < NEDGE) {
        int pos = atomicAdd(&g_cursor[ei[e]], 1);
        g_erow[pos] = e;
    }
}

// Vraw[j,n,c] = sum_h W_ih[j, n*16+h] * W_gcn[c,h]
__global__ void k_vraw(const float* __restrict__ Wih, const float* __restrict__ Wg) {
    __shared__ float wg[CIN * HGC];
    if (threadIdx.x < CIN * HGC) wg[threadIdx.x] = Wg[threadIdx.x];
    __syncthreads();
    int idx = blockIdx.x * blockDim.x + threadIdx.x; // 0 .. 1024*1000-1
    int j = idx / NNODE, n = idx % NNODE;
    float wih[HGC];
    const float4* p = (const float4*)(Wih + (size_t)j * WIHK + n * HGC);
#pragma unroll
    for (int q = 0; q < 4; q++) {
        float4 v = p[q];
        wih[q * 4 + 0] = v.x; wih[q * 4 + 1] = v.y; wih[q * 4 + 2] = v.z; wih[q * 4 + 3] = v.w;
    }
    float out[CIN];
#pragma unroll
    for (int c = 0; c < CIN; c++) {
        float s = 0.f;
#pragma unroll
        for (int h = 0; h < HGC; h++) s = fmaf(wih[h], wg[c * HGC + h], s);
        out[c] = s;
    }
    float4* o = (float4*)(g_Vraw + (size_t)j * KDIM + n * CIN);
    o[0] = make_float4(out[0], out[1], out[2], out[3]);
    o[1] = make_float4(out[4], out[5], out[6], out[7]);
}

// combined bias: b_ih + b_hh + sum_{n,h} W_ih[j,n*16+h]*b_gcn[h]
__global__ void k_bias(const float* __restrict__ Wih, const float* __restrict__ bg,
                       const float* __restrict__ bih, const float* __restrict__ bhh) {
    __shared__ float bgs[HGC];
    __shared__ float red[256];
    int j = blockIdx.x, tid = threadIdx.x;
    if (tid < HGC) bgs[tid] = bg[tid];
    __syncthreads();
    float s = 0.f;
    const float* w = Wih + (size_t)j * WIHK;
    for (int k = tid; k < WIHK; k += 256) s = fmaf(w[k], bgs[k & 15], s);
    red[tid] = s;
    __syncthreads();
    for (int off = 128; off > 0; off >>= 1) {
        if (tid < off) red[tid] += red[tid + off];
        __syncthreads();
    }
    if (tid == 0) g_biasfull[j] = red[0] + bih[j] + bhh[j];
}

// V0[j,n,c] = deginv[n]*Vraw[j,n,c] + sum_{e: row_e=n} norm_e * Vraw[j, col_e, c]
__global__ void k_v0(const int* __restrict__ ei) {
    int idx = blockIdx.x * blockDim.x + threadIdx.x; // 0 .. 1024*1000*8-1
    int c = idx & 7;
    int nj = idx >> 3;
    int n = nj % NNODE;
    int j = nj / NNODE;
    const float* vr = g_Vraw + (size_t)j * KDIM;
    float acc = g_deginv[n] * vr[n * CIN + c];
    int s = g_rowptr[n], epos = g_rowptr[n + 1];
    for (int p = s; p < epos; p++) {
        int e = g_erow[p];
        int col = ei[NEDGE + e];
        acc = fmaf(g_norm[e], vr[col * CIN + c], acc);
    }
    g_V0[(size_t)j * KDIM + n * CIN + c] = acc;
}

// ---------------- main GEMM: gates_in[t,b,j] = X[r,:] . W[j,:] + bias[j] ----------------
// X = x viewed as [2048, 8000]; row r = b*64+t. Block tile 64x128, block row 0 -> V0.
#define BM 64
#define BN 128
#define BK 16
__global__ void __launch_bounds__(256) k_gemm(const float* __restrict__ X) {
    int bm = blockIdx.x;   // 0..31 (== batch)
    int bn = blockIdx.y;   // 0..7
    const float* W = (bm == 0) ? g_V0 : g_Vraw;
    __shared__ float Xs[BK][BM];
    __shared__ float Ws[BK][BN];
    int tid = threadIdx.x;
    int tx = tid & 15, ty = tid >> 4;
    float acc[4][8];
#pragma unroll
    for (int i = 0; i < 4; i++)
#pragma unroll
        for (int p = 0; p < 8; p++) acc[i][p] = 0.f;

    const float* Xblk = X + (size_t)bm * BM * KDIM;
    const float* Wblk = W + (size_t)bn * BN * KDIM;

    int rowx = tid >> 2, kqx = tid & 3;

    for (int kb = 0; kb < KDIM; kb += BK) {
        {
            float4 v = *(const float4*)(Xblk + (size_t)rowx * KDIM + kb + kqx * 4);
            Xs[kqx * 4 + 0][rowx] = v.x; Xs[kqx * 4 + 1][rowx] = v.y;
            Xs[kqx * 4 + 2][rowx] = v.z; Xs[kqx * 4 + 3][rowx] = v.w;
        }
#pragma unroll
        for (int q = 0; q < 2; q++) {
            int lin = tid + q * 256;
            int jr = lin >> 2, kq = lin & 3;
            float4 v = *(const float4*)(Wblk + (size_t)jr * KDIM + kb + kq * 4);
            Ws[kq * 4 + 0][jr] = v.x; Ws[kq * 4 + 1][jr] = v.y;
            Ws[kq * 4 + 2][jr] = v.z; Ws[kq * 4 + 3][jr] = v.w;
        }
        __syncthreads();
#pragma unroll
        for (int k = 0; k < BK; k++) {
            float a[4], w[8];
            float4 av = *(const float4*)&Xs[k][ty * 4];
            a[0] = av.x; a[1] = av.y; a[2] = av.z; a[3] = av.w;
            float4 w0 = *(const float4*)&Ws[k][tx * 8];
            float4 w1 = *(const float4*)&Ws[k][tx * 8 + 4];
            w[0] = w0.x; w[1] = w0.y; w[2] = w0.z; w[3] = w0.w;
            w[4] = w1.x; w[5] = w1.y; w[6] = w1.z; w[7] = w1.w;
#pragma unroll
            for (int i = 0; i < 4; i++)
#pragma unroll
                for (int p = 0; p < 8; p++) acc[i][p] = fmaf(a[i], w[p], acc[i][p]);
        }
        __syncthreads();
    }
    // epilogue: g_gates[t][b][j] ; t = local row, b = bm
#pragma unroll
    for (int i = 0; i < 4; i++) {
        int t = ty * 4 + i;
#pragma unroll
        for (int p = 0; p < 8; p++) {
            int j = bn * BN + tx * 8 + p;
            g_gates[(size_t)t * (BATCH * JDIM) + bm * JDIM + j] = acc[i][p] + g_biasfull[j];
        }
    }
}

// ---------------- LSTM ----------------
__global__ void k_zero_state() {
    int i = blockIdx.x * blockDim.x + threadIdx.x;
    if (i < BATCH * HL) { g_h[0][i] = 0.f; g_c[0][i] = 0.f; }
}

__device__ __forceinline__ float sigf(float x) { return 1.0f / (1.0f + expf(-x)); }

// grid 8 blocks x 1024 thr; thread = (b fast 32, u_local 32); u = blk*32+ul
__global__ void __launch_bounds__(1024) k_step(const float* __restrict__ Whh, int t, int src) {
    __shared__ float hs[HL * 33];
    int tid = threadIdx.x;
    int b = tid & 31;
    int ul = tid >> 5;
    int u = blockIdx.x * 32 + ul;
    const float* hsrc = g_h[src];
    const float* csrc = g_c[src];
    float* hdst = g_h[1 - src];
    float* cdst = g_c[1 - src];
    for (int i = tid; i < BATCH * HL; i += 1024) {
        int bb = i >> 8, k = i & 255;
        hs[k * 33 + bb] = hsrc[i];
    }
    __syncthreads();
    float ai = 0.f, af = 0.f, ag = 0.f, ao = 0.f;
    const float* wi = Whh + (size_t)u * HL;
    const float* wf = Whh + (size_t)(HL + u) * HL;
    const float* wg = Whh + (size_t)(2 * HL + u) * HL;
    const float* wo = Whh + (size_t)(3 * HL + u) * HL;
#pragma unroll 8
    for (int k = 0; k < HL; k++) {
        float hv = hs[k * 33 + b];
        ai = fmaf(__ldg(wi + k), hv, ai);
        af = fmaf(__ldg(wf + k), hv, af);
        ag = fmaf(__ldg(wg + k), hv, ag);
        ao = fmaf(__ldg(wo + k), hv, ao);
    }
    const float* gin = g_gates + (size_t)t * (BATCH * JDIM) + b * JDIM;
    float gi = gin[u] + ai;
    float gf = gin[HL + u] + af;
    float gg = gin[2 * HL + u] + ag;
    float go = gin[3 * HL + u] + ao;
    float cp = csrc[b * HL + u];
    float cn = sigf(gf) * cp + sigf(gi) * tanhf(gg);
    float hn = sigf(go) * tanhf(cn);
    cdst[b * HL + u] = cn;
    hdst[b * HL + u] = hn;
}

// out[b,o] = h_last[b,:].W_proj[o,:] + b_proj[o]  (h_last in buffer 0)
__global__ void k_proj(const float* __restrict__ Wp, const float* __restrict__ bp,
                       float* __restrict__ out) {
    int tid = threadIdx.x;
    if (tid >= BATCH * NOUTD) return;
    int b = tid / NOUTD, o = tid % NOUTD;
    const float* h = g_h[0] + b * HL;
    const float* w = Wp + o * HL;
    float s = 0.f;
#pragma unroll 8
    for (int k = 0; k < HL; k++) s = fmaf(h[k], w[k], s);
    out[b * NOUTD + o] = s + bp[o];
}

// ---------------- launch ----------------
extern "C" void kernel_launch(void* const* d_in, const int* in_sizes, int n_in,
                              void* d_out, int out_size) {
    const float* x   = (const float*)d_in[0];
    const int*   ei  = (const int*)d_in[1];
    const float* ew  = (const float*)d_in[2];
    const float* Wg  = (const float*)d_in[3];
    const float* bg  = (const float*)d_in[4];
    const float* Wih = (const float*)d_in[5];
    const float* Whh = (const float*)d_in[6];
    const float* bih = (const float*)d_in[7];
    const float* bhh = (const float*)d_in[8];
    const float* Wp  = (const float*)d_in[9];
    const float* bp  = (const float*)d_in[10];
    float* out = (float*)d_out;

    (void)in_sizes; (void)n_in; (void)out_size;

    k_init<<<4, 256>>>();
    k_deg_accum<<<(NEDGE + 255) / 256, 256>>>(ei, ew);
    k_deg_finish<<<4, 256>>>();
    k_norm_rowcnt<<<(NEDGE + 255) / 256, 256>>>(ei, ew);
    k_scan<<<1, 1024>>>();
    k_scatter<<<(NEDGE + 255) / 256, 256>>>(ei);
    k_vraw<<<(JDIM * NNODE) / 256, 256>>>(Wih, Wg);
    k_bias<<<JDIM, 256>>>(Wih, bg, bih, bhh);
    k_v0<<<(JDIM * NNODE * CIN) / 256, 256>>>(ei);
    dim3 gg(BATCH, JDIM / BN);
    k_gemm<<<gg, 256>>>(x);
    k_zero_state<<<(BATCH * HL + 255) / 256, 256>>>();
    for (int t = 0; t < TSTEP; t++)
        k_step<<<8, 1024>>>(Whh, t, t & 1);
    k_proj<<<1, BATCH * NOUTD>>>(Wp, bp, out);
}

// round 2
// speedup vs baseline: 1.3769x; 1.3769x over previous
#include <cuda_runtime.h>
#include <math.h>

#define NNODE 1000
#define NEDGE 16000
#define BATCH 32
#define TSTEP 64
#define CIN   8
#define HGC   16
#define HL    256
#define NOUTD 24
#define KDIM  8000          // N*C
#define JDIM  1024          // 4*HL
#define WIHK  16000         // N*HG

// ---------------- scratch (device globals; no allocation) ----------------
__device__ __align__(16) float g_Vraw[JDIM * KDIM];           // 32.8 MB
__device__ __align__(16) float g_x0agg[TSTEP * KDIM];         // 2 MB (aggregated batch-0 x)
__device__ __align__(16) float g_gates[TSTEP * BATCH * JDIM]; // 8.4 MB
__device__ __align__(16) float g_WhhT[HL * JDIM];             // 1 MB transposed Whh
__device__ float g_biasfull[JDIM];
__device__ float g_deginv[NNODE];
__device__ float g_dis[NNODE];
__device__ float g_norm[NEDGE];
__device__ int   g_colcnt[NNODE + 1];
__device__ int   g_colptr[NNODE + 1];
__device__ int   g_cursor[NNODE];
__device__ int   g_ecol[NEDGE];          // edge ids grouped by col
__device__ __align__(16) float g_h[2][BATCH * HL];
__device__ __align__(16) float g_c[2][BATCH * HL];

// ---------------- small prep kernels ----------------
__global__ void k_init(const float* __restrict__ bih, const float* __restrict__ bhh) {
    int i = blockIdx.x * blockDim.x + threadIdx.x;
    if (i < NNODE) { g_deginv[i] = 1.0f; g_cursor[i] = 0; }
    if (i <= NNODE) g_colcnt[i] = 0;
    if (i < JDIM) g_biasfull[i] = bih[i] + bhh[i];
}

__global__ void k_deg_accum(const int* __restrict__ ei, const float* __restrict__ ew) {
    int e = blockIdx.x * blockDim.x + threadIdx.x;
    if (e < NEDGE) atomicAdd(&g_deginv[ei[NEDGE + e]], ew[e]); // col
}

__global__ void k_deg_finish() {
    int n = blockIdx.x * blockDim.x + threadIdx.x;
    if (n < NNODE) {
        float d = g_deginv[n];
        g_deginv[n] = 1.0f / d;
        g_dis[n] = rsqrtf(d);
    }
}

// norm per edge + column histogram
__global__ void k_norm_colcnt(const int* __restrict__ ei, const float* __restrict__ ew) {
    int e = blockIdx.x * blockDim.x + threadIdx.x;
    if (e < NEDGE) {
        int r = ei[e], c = ei[NEDGE + e];
        g_norm[e] = g_dis[r] * ew[e] * g_dis[c];
        atomicAdd(&g_colcnt[c], 1);
    }
}

// single-block exclusive scan of 1000 counts
__global__ void k_scan() {
    __shared__ int s[1024];
    int tid = threadIdx.x;
    int c = (tid < NNODE) ? g_colcnt[tid] : 0;
    s[tid] = c;
    for (int off = 1; off < 1024; off <<= 1) {
        __syncthreads();
        int v = (tid >= off) ? s[tid - off] : 0;
        __syncthreads();
        s[tid] += v;
    }
    __syncthreads();
    if (tid < NNODE) {
        int ex = s[tid] - c;
        g_colptr[tid] = ex;
        g_cursor[tid] = ex;
    }
    if (tid == 1023) g_colptr[NNODE] = s[1023];
}

__global__ void k_scatter(const int* __restrict__ ei) {
    int e = blockIdx.x * blockDim.x + threadIdx.x;
    if (e < NEDGE) {
        int pos = atomicAdd(&g_cursor[ei[NEDGE + e]], 1); // group by col
        g_ecol[pos] = e;
    }
}

// x0agg[t,m,c] = deginv[m]*x0[t,m,c] + sum_{e: col_e=m} norm_e * x0[t,row_e,c]
__global__ void k_x0agg(const float* __restrict__ x, const int* __restrict__ ei) {
    int idx = blockIdx.x * blockDim.x + threadIdx.x; // 0 .. 64*1000*8-1
    int c = idx & 7;
    int tm = idx >> 3;
    int m = tm % NNODE;
    int t = tm / NNODE;
    const float* xb = x + (size_t)t * KDIM;   // batch 0
    float acc = g_deginv[m] * xb[m * CIN + c];
    int s = g_colptr[m], epos = g_colptr[m + 1];
    for (int p = s; p < epos; p++) {
        int e = g_ecol[p];
        int r = ei[e];
        acc = fmaf(g_norm[e], xb[r * CIN + c], acc);
    }
    g_x0agg[(size_t)t * KDIM + m * CIN + c] = acc;
}

// Vraw[j,n,c] = sum_h W_ih[j, n*16+h] * W_gcn[c,h]; fused bias partial
__global__ void k_vraw(const float* __restrict__ Wih, const float* __restrict__ Wg,
                       const float* __restrict__ bg) {
    __shared__ float wg[CIN * HGC];
    __shared__ float bgs[HGC];
    if (threadIdx.x < CIN * HGC) wg[threadIdx.x] = Wg[threadIdx.x];
    if (threadIdx.x < HGC) bgs[threadIdx.x] = bg[threadIdx.x];
    __syncthreads();
    int idx = blockIdx.x * blockDim.x + threadIdx.x; // 0 .. 1024*1000-1
    int j = idx / NNODE, n = idx % NNODE;
    float wih[HGC];
    const float4* p = (const float4*)(Wih + (size_t)j * WIHK + n * HGC);
#pragma unroll
    for (int q = 0; q < 4; q++) {
        float4 v = p[q];
        wih[q * 4 + 0] = v.x; wih[q * 4 + 1] = v.y; wih[q * 4 + 2] = v.z; wih[q * 4 + 3] = v.w;
    }
    float out[CIN];
#pragma unroll
    for (int c = 0; c < CIN; c++) {
        float s = 0.f;
#pragma unroll
        for (int h = 0; h < HGC; h++) s = fmaf(wih[h], wg[c * HGC + h], s);
        out[c] = s;
    }
    float4* o = (float4*)(g_Vraw + (size_t)j * KDIM + n * CIN);
    o[0] = make_float4(out[0], out[1], out[2], out[3]);
    o[1] = make_float4(out[4], out[5], out[6], out[7]);
    // bias partial: sum_h wih[h]*bg[h]
    float bpart = 0.f;
#pragma unroll
    for (int h = 0; h < HGC; h++) bpart = fmaf(wih[h], bgs[h], bpart);
    atomicAdd(&g_biasfull[j], bpart);
}

// ---------------- main GEMM: gates[t,b,j] = A[r,:] . Vraw[j,:] + bias[j] ----------------
// A row r = b*64+t; bm==0 reads g_x0agg (aggregated batch-0), else x.
#define BM 64
#define BN 128
#define BK 16
__global__ void __launch_bounds__(256) k_gemm(const float* __restrict__ X) {
    int bm = blockIdx.x;   // 0..31 (== batch)
    int bn = blockIdx.y;   // 0..7
    __shared__ float Xs[BK][BM];
    __shared__ float Ws[BK][BN];
    int tid = threadIdx.x;
    int tx = tid & 15, ty = tid >> 4;
    float acc[4][8];
#pragma unroll
    for (int i = 0; i < 4; i++)
#pragma unroll
        for (int p = 0; p < 8; p++) acc[i][p] = 0.f;

    const float* Xblk = (bm == 0) ? g_x0agg : (X + (size_t)bm * BM * KDIM);
    const float* Wblk = g_Vraw + (size_t)bn * BN * KDIM;

    int rowx = tid >> 2, kqx = tid & 3;

    for (int kb = 0; kb < KDIM; kb += BK) {
        {
            float4 v = *(const float4*)(Xblk + (size_t)rowx * KDIM + kb + kqx * 4);
            Xs[kqx * 4 + 0][rowx] = v.x; Xs[kqx * 4 + 1][rowx] = v.y;
            Xs[kqx * 4 + 2][rowx] = v.z; Xs[kqx * 4 + 3][rowx] = v.w;
        }
#pragma unroll
        for (int q = 0; q < 2; q++) {
            int lin = tid + q * 256;
            int jr = lin >> 2, kq = lin & 3;
            float4 v = *(const float4*)(Wblk + (size_t)jr * KDIM + kb + kq * 4);
            Ws[kq * 4 + 0][jr] = v.x; Ws[kq * 4 + 1][jr] = v.y;
            Ws[kq * 4 + 2][jr] = v.z; Ws[kq * 4 + 3][jr] = v.w;
        }
        __syncthreads();
#pragma unroll
        for (int k = 0; k < BK; k++) {
            float a[4], w[8];
            float4 av = *(const float4*)&Xs[k][ty * 4];
            a[0] = av.x; a[1] = av.y; a[2] = av.z; a[3] = av.w;
            float4 w0 = *(const float4*)&Ws[k][tx * 8];
            float4 w1 = *(const float4*)&Ws[k][tx * 8 + 4];
            w[0] = w0.x; w[1] = w0.y; w[2] = w0.z; w[3] = w0.w;
            w[4] = w1.x; w[5] = w1.y; w[6] = w1.z; w[7] = w1.w;
#pragma unroll
            for (int i = 0; i < 4; i++)
#pragma unroll
                for (int p = 0; p < 8; p++) acc[i][p] = fmaf(a[i], w[p], acc[i][p]);
        }
        __syncthreads();
    }
#pragma unroll
    for (int i = 0; i < 4; i++) {
        int t = ty * 4 + i;
#pragma unroll
        for (int p = 0; p < 8; p++) {
            int j = bn * BN + tx * 8 + p;
            g_gates[(size_t)t * (BATCH * JDIM) + bm * JDIM + j] = acc[i][p] + g_biasfull[j];
        }
    }
}

// ---------------- LSTM ----------------
__global__ void k_zero_state() {
    int i = blockIdx.x * blockDim.x + threadIdx.x;
    if (i < BATCH * HL) { g_h[0][i] = 0.f; g_c[0][i] = 0.f; }
}

// transpose Whh [1024][256] -> WhhT [256][1024]
__global__ void k_whht(const float* __restrict__ Whh) {
    __shared__ float s[32][33];
    int jt = blockIdx.x * 32, kt = blockIdx.y * 32;
    int x = threadIdx.x, y = threadIdx.y; // 32x8
#pragma unroll
    for (int i = 0; i < 32; i += 8) s[y + i][x] = Whh[(size_t)(jt + y + i) * HL + kt + x];
    __syncthreads();
#pragma unroll
    for (int i = 0; i < 32; i += 8) g_WhhT[(size_t)(kt + y + i) * JDIM + jt + x] = s[x][y + i];
}

__device__ __forceinline__ float sigf(float x) { return 1.0f / (1.0f + expf(-x)); }

// grid (4 ug, 32 b) x 128 threads. warp = gate, each thread owns 2 j via float2.
__global__ void __launch_bounds__(128) k_step(int t, int src) {
    __shared__ float hs[HL];
    __shared__ float gbuf[4][64];
    int tid = threadIdx.x;
    int ug = blockIdx.x, b = blockIdx.y;
    const float* hsrc = g_h[src] + b * HL;
    hs[tid] = hsrc[tid];
    hs[tid + 128] = hsrc[tid + 128];
    __syncthreads();
    int warp = tid >> 5, lane = tid & 31;
    int jbase = warp * 256 + ug * 64 + lane * 2;
    float accx = 0.f, accy = 0.f;
    const float* wp = g_WhhT + jbase;
#pragma unroll 16
    for (int k = 0; k < HL; k++) {
        float hk = hs[k];
        float2 w = *(const float2*)(wp + (size_t)k * JDIM);
        accx = fmaf(w.x, hk, accx);
        accy = fmaf(w.y, hk, accy);
    }
    const float* gin = g_gates + (size_t)t * (BATCH * JDIM) + b * JDIM;
    float2 gv = *(const float2*)(gin + jbase);
    accx += gv.x; accy += gv.y;
    gbuf[warp][lane * 2] = accx;
    gbuf[warp][lane * 2 + 1] = accy;
    __syncthreads();
    if (tid < 64) {
        int u = ug * 64 + tid;
        float gi = gbuf[0][tid], gf = gbuf[1][tid], gg = gbuf[2][tid], go = gbuf[3][tid];
        float cp = g_c[src][b * HL + u];
        float cn = sigf(gf) * cp + sigf(gi) * tanhf(gg);
        float hn = sigf(go) * tanhf(cn);
        g_c[1 - src][b * HL + u] = cn;
        g_h[1 - src][b * HL + u] = hn;
    }
}

// out[b,o] = h_last[b,:].W_proj[o,:] + b_proj[o]  (h_last in buffer 0)
__global__ void k_proj(const float* __restrict__ Wp, const float* __restrict__ bp,
                       float* __restrict__ out) {
    int tid = threadIdx.x;
    if (tid >= BATCH * NOUTD) return;
    int b = tid / NOUTD, o = tid % NOUTD;
    const float* h = g_h[0] + b * HL;
    const float* w = Wp + o * HL;
    float s = 0.f;
#pragma unroll 8
    for (int k = 0; k < HL; k++) s = fmaf(h[k], w[k], s);
    out[b * NOUTD + o] = s + bp[o];
}

// ---------------- launch ----------------
extern "C" void kernel_launch(void* const* d_in, const int* in_sizes, int n_in,
                              void* d_out, int out_size) {
    const float* x   = (const float*)d_in[0];
    const int*   ei  = (const int*)d_in[1];
    const float* ew  = (const float*)d_in[2];
    const float* Wg  = (const float*)d_in[3];
    const float* bg  = (const float*)d_in[4];
    const float* Wih = (const float*)d_in[5];
    const float* Whh = (const float*)d_in[6];
    const float* bih = (const float*)d_in[7];
    const float* bhh = (const float*)d_in[8];
    const float* Wp  = (const float*)d_in[9];
    const float* bp  = (const float*)d_in[10];
    float* out = (float*)d_out;

    (void)in_sizes; (void)n_in; (void)out_size;

    k_init<<<4, 256>>>(bih, bhh);
    k_deg_accum<<<(NEDGE + 255) / 256, 256>>>(ei, ew);
    k_deg_finish<<<4, 256>>>();
    k_norm_colcnt<<<(NEDGE + 255) / 256, 256>>>(ei, ew);
    k_scan<<<1, 1024>>>();
    k_scatter<<<(NEDGE + 255) / 256, 256>>>(ei);
    k_x0agg<<<(TSTEP * NNODE * CIN + 255) / 256, 256>>>(x, ei);
    k_vraw<<<(JDIM * NNODE) / 256, 256>>>(Wih, Wg, bg);
    k_whht<<<dim3(32, 8), dim3(32, 8)>>>(Whh);
    dim3 gg(BATCH, JDIM / BN);
    k_gemm<<<gg, 256>>>(x);
    k_zero_state<<<(BATCH * HL + 255) / 256, 256>>>();
    for (int t = 0; t < TSTEP; t++)
        k_step<<<dim3(4, BATCH), 128>>>(t, t & 1);
    k_proj<<<1, BATCH * NOUTD>>>(Wp, bp, out);
}

// round 3
// speedup vs baseline: 1.3877x; 1.0078x over previous
#include <cuda_runtime.h>
#include <math.h>

#define NNODE 1000
#define NEDGE 16000
#define BATCH 32
#define TSTEP 64
#define CIN   8
#define HGC   16
#define HL    256
#define NOUTD 24
#define KDIM  8000          // N*C
#define JDIM  1024          // 4*HL
#define WIHK  16000         // N*HG

// ---------------- scratch (device globals; no allocation) ----------------
__device__ __align__(16) float g_Vraw[JDIM * KDIM];           // 32.8 MB
__device__ __align__(16) float g_x0agg[TSTEP * KDIM];         // 2 MB (aggregated batch-0 x)
__device__ __align__(16) float g_gates[TSTEP * BATCH * JDIM]; // 8.4 MB
__device__ __align__(16) float g_WhhT[HL * JDIM];             // 1 MB transposed Whh
__device__ float g_biasfull[JDIM];
__device__ float g_deginv[NNODE];
__device__ float g_dis[NNODE];
__device__ float g_norm[NEDGE];
__device__ int   g_colcnt[NNODE + 1];
__device__ int   g_colptr[NNODE + 1];
__device__ int   g_cursor[NNODE];
__device__ int   g_ecol[NEDGE];          // edge ids grouped by col
__device__ __align__(16) float g_h[2][BATCH * HL];
__device__ __align__(16) float g_c[2][BATCH * HL];

// ---------------- small prep kernels ----------------
__global__ void k_init(const float* __restrict__ bih, const float* __restrict__ bhh) {
    int i = blockIdx.x * blockDim.x + threadIdx.x;
    if (i < NNODE) { g_deginv[i] = 1.0f; g_cursor[i] = 0; }
    if (i <= NNODE) g_colcnt[i] = 0;
    if (i < JDIM) g_biasfull[i] = bih[i] + bhh[i];
}

__global__ void k_deg_accum(const int* __restrict__ ei, const float* __restrict__ ew) {
    int e = blockIdx.x * blockDim.x + threadIdx.x;
    if (e < NEDGE) atomicAdd(&g_deginv[ei[NEDGE + e]], ew[e]); // col
}

__global__ void k_deg_finish() {
    int n = blockIdx.x * blockDim.x + threadIdx.x;
    if (n < NNODE) {
        float d = g_deginv[n];
        g_deginv[n] = 1.0f / d;
        g_dis[n] = rsqrtf(d);
    }
}

// norm per edge + column histogram
__global__ void k_norm_colcnt(const int* __restrict__ ei, const float* __restrict__ ew) {
    int e = blockIdx.x * blockDim.x + threadIdx.x;
    if (e < NEDGE) {
        int r = ei[e], c = ei[NEDGE + e];
        g_norm[e] = g_dis[r] * ew[e] * g_dis[c];
        atomicAdd(&g_colcnt[c], 1);
    }
}

// single-block exclusive scan of 1000 counts
__global__ void k_scan() {
    __shared__ int s[1024];
    int tid = threadIdx.x;
    int c = (tid < NNODE) ? g_colcnt[tid] : 0;
    s[tid] = c;
    for (int off = 1; off < 1024; off <<= 1) {
        __syncthreads();
        int v = (tid >= off) ? s[tid - off] : 0;
        __syncthreads();
        s[tid] += v;
    }
    __syncthreads();
    if (tid < NNODE) {
        int ex = s[tid] - c;
        g_colptr[tid] = ex;
        g_cursor[tid] = ex;
    }
    if (tid == 1023) g_colptr[NNODE] = s[1023];
}

__global__ void k_scatter(const int* __restrict__ ei) {
    int e = blockIdx.x * blockDim.x + threadIdx.x;
    if (e < NEDGE) {
        int pos = atomicAdd(&g_cursor[ei[NEDGE + e]], 1); // group by col
        g_ecol[pos] = e;
    }
}

// x0agg[t,m,c] = deginv[m]*x0[t,m,c] + sum_{e: col_e=m} norm_e * x0[t,row_e,c]
__global__ void k_x0agg(const float* __restrict__ x, const int* __restrict__ ei) {
    int idx = blockIdx.x * blockDim.x + threadIdx.x; // 0 .. 64*1000*8-1
    int c = idx & 7;
    int tm = idx >> 3;
    int m = tm % NNODE;
    int t = tm / NNODE;
    const float* xb = x + (size_t)t * KDIM;   // batch 0
    float acc = g_deginv[m] * xb[m * CIN + c];
    int s = g_colptr[m], epos = g_colptr[m + 1];
    for (int p = s; p < epos; p++) {
        int e = g_ecol[p];
        int r = ei[e];
        acc = fmaf(g_norm[e], xb[r * CIN + c], acc);
    }
    g_x0agg[(size_t)t * KDIM + m * CIN + c] = acc;
}

// Vraw[j,n,c] = sum_h W_ih[j, n*16+h] * W_gcn[c,h]; fused bias partial
__global__ void k_vraw(const float* __restrict__ Wih, const float* __restrict__ Wg,
                       const float* __restrict__ bg) {
    __shared__ float wg[CIN * HGC];
    __shared__ float bgs[HGC];
    if (threadIdx.x < CIN * HGC) wg[threadIdx.x] = Wg[threadIdx.x];
    if (threadIdx.x < HGC) bgs[threadIdx.x] = bg[threadIdx.x];
    __syncthreads();
    int idx = blockIdx.x * blockDim.x + threadIdx.x; // 0 .. 1024*1000-1
    int j = idx / NNODE, n = idx % NNODE;
    float wih[HGC];
    const float4* p = (const float4*)(Wih + (size_t)j * WIHK + n * HGC);
#pragma unroll
    for (int q = 0; q < 4; q++) {
        float4 v = p[q];
        wih[q * 4 + 0] = v.x; wih[q * 4 + 1] = v.y; wih[q * 4 + 2] = v.z; wih[q * 4 + 3] = v.w;
    }
    float out[CIN];
#pragma unroll
    for (int c = 0; c < CIN; c++) {
        float s = 0.f;
#pragma unroll
        for (int h = 0; h < HGC; h++) s = fmaf(wih[h], wg[c * HGC + h], s);
        out[c] = s;
    }
    float4* o = (float4*)(g_Vraw + (size_t)j * KDIM + n * CIN);
    o[0] = make_float4(out[0], out[1], out[2], out[3]);
    o[1] = make_float4(out[4], out[5], out[6], out[7]);
    // bias partial: sum_h wih[h]*bg[h]
    float bpart = 0.f;
#pragma unroll
    for (int h = 0; h < HGC; h++) bpart = fmaf(wih[h], bgs[h], bpart);
    atomicAdd(&g_biasfull[j], bpart);
}

// ---------------- main GEMM: gates[t,b,j] = A[r,:] . Vraw[j,:] + bias[j] ----------------
// A row r = b*64+t; bm==0 reads g_x0agg (aggregated batch-0), else x.
#define BM 64
#define BN 128
#define BK 16
__global__ void __launch_bounds__(256) k_gemm(const float* __restrict__ X) {
    int bm = blockIdx.x;   // 0..31 (== batch)
    int bn = blockIdx.y;   // 0..7
    __shared__ float Xs[BK][BM];
    __shared__ float Ws[BK][BN];
    int tid = threadIdx.x;
    int tx = tid & 15, ty = tid >> 4;
    float acc[4][8];
#pragma unroll
    for (int i = 0; i < 4; i++)
#pragma unroll
        for (int p = 0; p < 8; p++) acc[i][p] = 0.f;

    const float* Xblk = (bm == 0) ? g_x0agg : (X + (size_t)bm * BM * KDIM);
    const float* Wblk = g_Vraw + (size_t)bn * BN * KDIM;

    int rowx = tid >> 2, kqx = tid & 3;

    for (int kb = 0; kb < KDIM; kb += BK) {
        {
            float4 v = *(const float4*)(Xblk + (size_t)rowx * KDIM + kb + kqx * 4);
            Xs[kqx * 4 + 0][rowx] = v.x; Xs[kqx * 4 + 1][rowx] = v.y;
            Xs[kqx * 4 + 2][rowx] = v.z; Xs[kqx * 4 + 3][rowx] = v.w;
        }
#pragma unroll
        for (int q = 0; q < 2; q++) {
            int lin = tid + q * 256;
            int jr = lin >> 2, kq = lin & 3;
            float4 v = *(const float4*)(Wblk + (size_t)jr * KDIM + kb + kq * 4);
            Ws[kq * 4 + 0][jr] = v.x; Ws[kq * 4 + 1][jr] = v.y;
            Ws[kq * 4 + 2][jr] = v.z; Ws[kq * 4 + 3][jr] = v.w;
        }
        __syncthreads();
#pragma unroll
        for (int k = 0; k < BK; k++) {
            float a[4], w[8];
            float4 av = *(const float4*)&Xs[k][ty * 4];
            a[0] = av.x; a[1] = av.y; a[2] = av.z; a[3] = av.w;
            float4 w0 = *(const float4*)&Ws[k][tx * 8];
            float4 w1 = *(const float4*)&Ws[k][tx * 8 + 4];
            w[0] = w0.x; w[1] = w0.y; w[2] = w0.z; w[3] = w0.w;
            w[4] = w1.x; w[5] = w1.y; w[6] = w1.z; w[7] = w1.w;
#pragma unroll
            for (int i = 0; i < 4; i++)
#pragma unroll
                for (int p = 0; p < 8; p++) acc[i][p] = fmaf(a[i], w[p], acc[i][p]);
        }
        __syncthreads();
    }
#pragma unroll
    for (int i = 0; i < 4; i++) {
        int t = ty * 4 + i;
#pragma unroll
        for (int p = 0; p < 8; p++) {
            int j = bn * BN + tx * 8 + p;
            g_gates[(size_t)t * (BATCH * JDIM) + bm * JDIM + j] = acc[i][p] + g_biasfull[j];
        }
    }
}

// ---------------- LSTM ----------------
__global__ void k_zero_state() {
    int i = blockIdx.x * blockDim.x + threadIdx.x;
    if (i < BATCH * HL) { g_h[0][i] = 0.f; g_c[0][i] = 0.f; }
}

// transpose Whh [1024][256] -> WhhT [256][1024]
__global__ void k_whht(const float* __restrict__ Whh) {
    __shared__ float s[32][33];
    int jt = blockIdx.x * 32, kt = blockIdx.y * 32;
    int x = threadIdx.x, y = threadIdx.y; // 32x8
#pragma unroll
    for (int i = 0; i < 32; i += 8) s[y + i][x] = Whh[(size_t)(jt + y + i) * HL + kt + x];
    __syncthreads();
#pragma unroll
    for (int i = 0; i < 32; i += 8) g_WhhT[(size_t)(kt + y + i) * JDIM + jt + x] = s[x][y + i];
}

__device__ __forceinline__ float sigf(float x) { return 1.0f / (1.0f + expf(-x)); }

// grid (4 ug, 32 b) x 128 threads. warp = gate, each thread owns 2 j via float2.
__global__ void __launch_bounds__(128) k_step(int t, int src) {
    __shared__ float hs[HL];
    __shared__ float gbuf[4][64];
    int tid = threadIdx.x;
    int ug = blockIdx.x, b = blockIdx.y;
    const float* hsrc = g_h[src] + b * HL;
    hs[tid] = hsrc[tid];
    hs[tid + 128] = hsrc[tid + 128];
    __syncthreads();
    int warp = tid >> 5, lane = tid & 31;
    int jbase = warp * 256 + ug * 64 + lane * 2;
    float accx = 0.f, accy = 0.f;
    const float* wp = g_WhhT + jbase;
#pragma unroll 16
    for (int k = 0; k < HL; k++) {
        float hk = hs[k];
        float2 w = *(const float2*)(wp + (size_t)k * JDIM);
        accx = fmaf(w.x, hk, accx);
        accy = fmaf(w.y, hk, accy);
    }
    const float* gin = g_gates + (size_t)t * (BATCH * JDIM) + b * JDIM;
    float2 gv = *(const float2*)(gin + jbase);
    accx += gv.x; accy += gv.y;
    gbuf[warp][lane * 2] = accx;
    gbuf[warp][lane * 2 + 1] = accy;
    __syncthreads();
    if (tid < 64) {
        int u = ug * 64 + tid;
        float gi = gbuf[0][tid], gf = gbuf[1][tid], gg = gbuf[2][tid], go = gbuf[3][tid];
        float cp = g_c[src][b * HL + u];
        float cn = sigf(gf) * cp + sigf(gi) * tanhf(gg);
        float hn = sigf(go) * tanhf(cn);
        g_c[1 - src][b * HL + u] = cn;
        g_h[1 - src][b * HL + u] = hn;
    }
}

// out[b,o] = h_last[b,:].W_proj[o,:] + b_proj[o]  (h_last in buffer 0)
__global__ void k_proj(const float* __restrict__ Wp, const float* __restrict__ bp,
                       float* __restrict__ out) {
    int tid = threadIdx.x;
    if (tid >= BATCH * NOUTD) return;
    int b = tid / NOUTD, o = tid % NOUTD;
    const float* h = g_h[0] + b * HL;
    const float* w = Wp + o * HL;
    float s = 0.f;
#pragma unroll 8
    for (int k = 0; k < HL; k++) s = fmaf(h[k], w[k], s);
    out[b * NOUTD + o] = s + bp[o];
}

// ---------------- launch ----------------
extern "C" void kernel_launch(void* const* d_in, const int* in_sizes, int n_in,
                              void* d_out, int out_size) {
    const float* x   = (const float*)d_in[0];
    const int*   ei  = (const int*)d_in[1];
    const float* ew  = (const float*)d_in[2];
    const float* Wg  = (const float*)d_in[3];
    const float* bg  = (const float*)d_in[4];
    const float* Wih = (const float*)d_in[5];
    const float* Whh = (const float*)d_in[6];
    const float* bih = (const float*)d_in[7];
    const float* bhh = (const float*)d_in[8];
    const float* Wp  = (const float*)d_in[9];
    const float* bp  = (const float*)d_in[10];
    float* out = (float*)d_out;

    (void)in_sizes; (void)n_in; (void)out_size;

    k_init<<<4, 256>>>(bih, bhh);
    k_deg_accum<<<(NEDGE + 255) / 256, 256>>>(ei, ew);
    k_deg_finish<<<4, 256>>>();
    k_norm_colcnt<<<(NEDGE + 255) / 256, 256>>>(ei, ew);
    k_scan<<<1, 1024>>>();
    k_scatter<<<(NEDGE + 255) / 256, 256>>>(ei);
    k_x0agg<<<(TSTEP * NNODE * CIN + 255) / 256, 256>>>(x, ei);
    k_vraw<<<(JDIM * NNODE) / 256, 256>>>(Wih, Wg, bg);
    k_whht<<<dim3(32, 8), dim3(32, 8)>>>(Whh);
    dim3 gg(BATCH, JDIM / BN);
    k_gemm<<<gg, 256>>>(x);
    k_zero_state<<<(BATCH * HL + 255) / 256, 256>>>();
    for (int t = 0; t < TSTEP; t++)
        k_step<<<dim3(4, BATCH), 128>>>(t, t & 1);
    k_proj<<<1, BATCH * NOUTD>>>(Wp, bp, out);
}

// round 4
// speedup vs baseline: 1.4745x; 1.0626x over previous
#include <cuda_runtime.h>
#include <math.h>

#define NNODE 1000
#define NEDGE 16000
#define BATCH 32
#define TSTEP 64
#define CIN   8
#define HGC   16
#define HL    256
#define NOUTD 24
#define KDIM  8000          // N*C
#define JDIM  1024          // 4*HL
#define WIHK  16000         // N*HG

typedef unsigned long long u64;

// ---------------- scratch (device globals; no allocation) ----------------
__device__ __align__(16) float g_Vraw[JDIM * KDIM];           // 32.8 MB
__device__ __align__(16) float g_x0agg[TSTEP * KDIM];         // 2 MB
__device__ __align__(16) float g_gates[TSTEP * BATCH * JDIM]; // 8.4 MB
__device__ float g_biasfull[JDIM];
__device__ float g_deginv[NNODE];
__device__ float g_dis[NNODE];
__device__ float g_norm[NEDGE];
__device__ int   g_colcnt[NNODE + 1];
__device__ int   g_colptr[NNODE + 1];
__device__ int   g_cursor[NNODE];
__device__ int   g_ecol[NEDGE];
__device__ __align__(16) float g_hst[2][BATCH * HL];
__device__ int   g_bcnt;
__device__ int   g_bgen;

// ---------------- f32x2 helpers ----------------
__device__ __forceinline__ u64 pack2(float lo, float hi) {
    u64 r; asm("mov.b64 %0, {%1, %2};" : "=l"(r) : "f"(lo), "f"(hi)); return r;
}
__device__ __forceinline__ void unpack2(float& lo, float& hi, u64 v) {
    asm("mov.b64 {%0, %1}, %2;" : "=f"(lo), "=f"(hi) : "l"(v));
}
#define FFMA2(acc, a, w) asm("fma.rn.f32x2 %0, %1, %2, %0;" : "+l"(acc) : "l"(a), "l"(w))

// ---------------- small prep kernels ----------------
__global__ void k_init(const float* __restrict__ bih, const float* __restrict__ bhh) {
    int i = blockIdx.x * blockDim.x + threadIdx.x;  // 0..8191
    if (i < NNODE) { g_deginv[i] = 1.0f; g_cursor[i] = 0; }
    if (i <= NNODE) g_colcnt[i] = 0;
    if (i < JDIM) g_biasfull[i] = bih[i] + bhh[i];
    if (i < BATCH * HL) g_hst[0][i] = 0.f;
    if (i == 0) { g_bcnt = 0; g_bgen = 0; }
}

__global__ void k_deg_accum(const int* __restrict__ ei, const float* __restrict__ ew) {
    int e = blockIdx.x * blockDim.x + threadIdx.x;
    if (e < NEDGE) atomicAdd(&g_deginv[ei[NEDGE + e]], ew[e]); // col
}

__global__ void k_deg_finish() {
    int n = blockIdx.x * blockDim.x + threadIdx.x;
    if (n < NNODE) {
        float d = g_deginv[n];
        g_deginv[n] = 1.0f / d;
        g_dis[n] = rsqrtf(d);
    }
}

__global__ void k_norm_colcnt(const int* __restrict__ ei, const float* __restrict__ ew) {
    int e = blockIdx.x * blockDim.x + threadIdx.x;
    if (e < NEDGE) {
        int r = ei[e], c = ei[NEDGE + e];
        g_norm[e] = g_dis[r] * ew[e] * g_dis[c];
        atomicAdd(&g_colcnt[c], 1);
    }
}

__global__ void k_scan() {
    __shared__ int s[1024];
    int tid = threadIdx.x;
    int c = (tid < NNODE) ? g_colcnt[tid] : 0;
    s[tid] = c;
    for (int off = 1; off < 1024; off <<= 1) {
        __syncthreads();
        int v = (tid >= off) ? s[tid - off] : 0;
        __syncthreads();
        s[tid] += v;
    }
    __syncthreads();
    if (tid < NNODE) {
        int ex = s[tid] - c;
        g_colptr[tid] = ex;
        g_cursor[tid] = ex;
    }
    if (tid == 1023) g_colptr[NNODE] = s[1023];
}

__global__ void k_scatter(const int* __restrict__ ei) {
    int e = blockIdx.x * blockDim.x + threadIdx.x;
    if (e < NEDGE) {
        int pos = atomicAdd(&g_cursor[ei[NEDGE + e]], 1);
        g_ecol[pos] = e;
    }
}

// x0agg[t,m,c] = deginv[m]*x0[t,m,c] + sum_{e: col_e=m} norm_e * x0[t,row_e,c]
__global__ void k_x0agg(const float* __restrict__ x, const int* __restrict__ ei) {
    int idx = blockIdx.x * blockDim.x + threadIdx.x;
    int c = idx & 7;
    int tm = idx >> 3;
    int m = tm % NNODE;
    int t = tm / NNODE;
    const float* xb = x + (size_t)t * KDIM;
    float acc = g_deginv[m] * xb[m * CIN + c];
    int s = g_colptr[m], epos = g_colptr[m + 1];
    for (int p = s; p < epos; p++) {
        int e = g_ecol[p];
        int r = ei[e];
        acc = fmaf(g_norm[e], xb[r * CIN + c], acc);
    }
    g_x0agg[(size_t)t * KDIM + m * CIN + c] = acc;
}

// Vraw[j,n,c] = sum_h W_ih[j,n*16+h]*W_gcn[c,h]; fused bias partial
__global__ void k_vraw(const float* __restrict__ Wih, const float* __restrict__ Wg,
                       const float* __restrict__ bg) {
    __shared__ float wg[CIN * HGC];
    __shared__ float bgs[HGC];
    if (threadIdx.x < CIN * HGC) wg[threadIdx.x] = Wg[threadIdx.x];
    if (threadIdx.x < HGC) bgs[threadIdx.x] = bg[threadIdx.x];
    __syncthreads();
    int idx = blockIdx.x * blockDim.x + threadIdx.x;
    int j = idx / NNODE, n = idx % NNODE;
    float wih[HGC];
    const float4* p = (const float4*)(Wih + (size_t)j * WIHK + n * HGC);
#pragma unroll
    for (int q = 0; q < 4; q++) {
        float4 v = p[q];
        wih[q * 4 + 0] = v.x; wih[q * 4 + 1] = v.y; wih[q * 4 + 2] = v.z; wih[q * 4 + 3] = v.w;
    }
    float out[CIN];
#pragma unroll
    for (int c = 0; c < CIN; c++) {
        float s = 0.f;
#pragma unroll
        for (int h = 0; h < HGC; h++) s = fmaf(wih[h], wg[c * HGC + h], s);
        out[c] = s;
    }
    float4* o = (float4*)(g_Vraw + (size_t)j * KDIM + n * CIN);
    o[0] = make_float4(out[0], out[1], out[2], out[3]);
    o[1] = make_float4(out[4], out[5], out[6], out[7]);
    float bpart = 0.f;
#pragma unroll
    for (int h = 0; h < HGC; h++) bpart = fmaf(wih[h], bgs[h], bpart);
    atomicAdd(&g_biasfull[j], bpart);
}

// ---------------- main GEMM (f32x2 packed FMA) ----------------
#define BM 64
#define BN 128
#define BK 16
__global__ void __launch_bounds__(256) k_gemm(const float* __restrict__ X) {
    int bm = blockIdx.x;   // batch
    int bn = blockIdx.y;   // j-tile
    __shared__ __align__(16) u64   Xs2[BK][BM];   // duplicated packs (a,a)
    __shared__ __align__(16) float Ws[BK][BN];
    int tid = threadIdx.x;
    int tx = tid & 15, ty = tid >> 4;
    u64 acc[4][4];
#pragma unroll
    for (int i = 0; i < 4; i++)
#pragma unroll
        for (int p = 0; p < 4; p++) acc[i][p] = 0ull;

    const float* Xblk = (bm == 0) ? g_x0agg : (X + (size_t)bm * BM * KDIM);
    const float* Wblk = g_Vraw + (size_t)bn * BN * KDIM;

    int rowx = tid >> 2, kqx = tid & 3;

    for (int kb = 0; kb < KDIM; kb += BK) {
        {
            float4 v = *(const float4*)(Xblk + (size_t)rowx * KDIM + kb + kqx * 4);
            Xs2[kqx * 4 + 0][rowx] = pack2(v.x, v.x);
            Xs2[kqx * 4 + 1][rowx] = pack2(v.y, v.y);
            Xs2[kqx * 4 + 2][rowx] = pack2(v.z, v.z);
            Xs2[kqx * 4 + 3][rowx] = pack2(v.w, v.w);
        }
#pragma unroll
        for (int q = 0; q < 2; q++) {
            int lin = tid + q * 256;
            int jr = lin >> 2, kq = lin & 3;
            float4 v = *(const float4*)(Wblk + (size_t)jr * KDIM + kb + kq * 4);
            Ws[kq * 4 + 0][jr] = v.x; Ws[kq * 4 + 1][jr] = v.y;
            Ws[kq * 4 + 2][jr] = v.z; Ws[kq * 4 + 3][jr] = v.w;
        }
        __syncthreads();
#pragma unroll
        for (int k = 0; k < BK; k++) {
            ulonglong2 a01 = *(const ulonglong2*)&Xs2[k][ty * 4];
            ulonglong2 a23 = *(const ulonglong2*)&Xs2[k][ty * 4 + 2];
            ulonglong2 w01 = *(const ulonglong2*)&Ws[k][tx * 8];      // (w0,w1),(w2,w3)
            ulonglong2 w23 = *(const ulonglong2*)&Ws[k][tx * 8 + 4];  // (w4,w5),(w6,w7)
            FFMA2(acc[0][0], a01.x, w01.x); FFMA2(acc[0][1], a01.x, w01.y);
            FFMA2(acc[0][2], a01.x, w23.x); FFMA2(acc[0][3], a01.x, w23.y);
            FFMA2(acc[1][0], a01.y, w01.x); FFMA2(acc[1][1], a01.y, w01.y);
            FFMA2(acc[1][2], a01.y, w23.x); FFMA2(acc[1][3], a01.y, w23.y);
            FFMA2(acc[2][0], a23.x, w01.x); FFMA2(acc[2][1], a23.x, w01.y);
            FFMA2(acc[2][2], a23.x, w23.x); FFMA2(acc[2][3], a23.x, w23.y);
            FFMA2(acc[3][0], a23.y, w01.x); FFMA2(acc[3][1], a23.y, w01.y);
            FFMA2(acc[3][2], a23.y, w23.x); FFMA2(acc[3][3], a23.y, w23.y);
        }
        __syncthreads();
    }
#pragma unroll
    for (int i = 0; i < 4; i++) {
        int t = ty * 4 + i;
        float* gout = g_gates + (size_t)t * (BATCH * JDIM) + bm * JDIM;
#pragma unroll
        for (int p = 0; p < 4; p++) {
            int j = bn * BN + tx * 8 + p * 2;
            float lo, hi; unpack2(lo, hi, acc[i][p]);
            float2 r = make_float2(lo + g_biasfull[j], hi + g_biasfull[j + 1]);
            *(float2*)(gout + j) = r;
        }
    }
}

// ---------------- persistent LSTM ----------------
__device__ __forceinline__ float sigf(float x) { return 1.0f / (1.0f + expf(-x)); }

#define LBLK 64   // blocks; each owns 4 units
__global__ void __launch_bounds__(128) k_lstm(const float* __restrict__ Whh) {
    __shared__ __align__(16) float Wsm[16][HL];       // 16 KB (rows: jj*4+g)
    __shared__ u64 hp[HL / 2][33];                    // packed h, padded
    int tid = threadIdx.x;
    int u0 = blockIdx.x * 4;
    // load Whh slice once
    for (int i = tid; i < 16 * HL; i += 128) {
        int r = i >> 8, k = i & 255;
        int jj = r >> 2, g = r & 3;
        Wsm[r][k] = Whh[(size_t)(g * HL + u0 + jj) * HL + k];
    }
    int b = tid & 31, jj = tid >> 5;   // warp == jj
    int u = u0 + jj;
    float creg = 0.f;
    int mygen = 0;

    for (int t = 0; t < TSTEP; t++) {
        int p = t & 1;
        __syncthreads();
        const float* hsrc = g_hst[p];
        for (int i = tid; i < BATCH * (HL / 2); i += 128) {
            int k2 = i & 127, bb = i >> 7;
            float2 hv = *(const float2*)(hsrc + bb * HL + k2 * 2);
            hp[k2][bb] = pack2(hv.x, hv.y);
        }
        __syncthreads();
        u64 acc[4] = {0ull, 0ull, 0ull, 0ull};
#pragma unroll 4
        for (int k2 = 0; k2 < HL / 2; k2++) {
            u64 h2 = hp[k2][b];
#pragma unroll
            for (int g = 0; g < 4; g++) {
                u64 w2 = *(const u64*)&Wsm[jj * 4 + g][k2 * 2];
                FFMA2(acc[g], h2, w2);
            }
        }
        const float* gin = g_gates + (size_t)t * (BATCH * JDIM) + b * JDIM;
        float gv[4];
#pragma unroll
        for (int g = 0; g < 4; g++) {
            float lo, hi; unpack2(lo, hi, acc[g]);
            gv[g] = lo + hi + __ldg(gin + g * HL + u);
        }
        float cn = sigf(gv[1]) * creg + sigf(gv[0]) * tanhf(gv[2]);
        float hn = sigf(gv[3]) * tanhf(cn);
        creg = cn;
        g_hst[1 - p][b * HL + u] = hn;
        // ---- grid barrier ----
        __threadfence();
        __syncthreads();
        if (tid == 0) {
            int old = atomicAdd(&g_bcnt, 1);
            if (old == LBLK - 1) {
                atomicExch(&g_bcnt, 0);
                __threadfence();
                ((volatile int*)&g_bgen)[0] = mygen + 1;
            } else {
                while (((volatile int*)&g_bgen)[0] <= mygen) { }
            }
        }
        __syncthreads();
        __threadfence();
        mygen++;
    }
}

// out[b,o] = h_last[b,:].W_proj[o,:] + b_proj[o]   (h_last = g_hst[0])
__global__ void k_proj(const float* __restrict__ Wp, const float* __restrict__ bp,
                       float* __restrict__ out) {
    int tid = threadIdx.x;
    if (tid >= BATCH * NOUTD) return;
    int b = tid / NOUTD, o = tid % NOUTD;
    const float* h = g_hst[0] + b * HL;
    const float* w = Wp + o * HL;
    float s = 0.f;
#pragma unroll 8
    for (int k = 0; k < HL; k++) s = fmaf(h[k], w[k], s);
    out[b * NOUTD + o] = s + bp[o];
}

// ---------------- launch ----------------
extern "C" void kernel_launch(void* const* d_in, const int* in_sizes, int n_in,
                              void* d_out, int out_size) {
    const float* x   = (const float*)d_in[0];
    const int*   ei  = (const int*)d_in[1];
    const float* ew  = (const float*)d_in[2];
    const float* Wg  = (const float*)d_in[3];
    const float* bg  = (const float*)d_in[4];
    const float* Wih = (const float*)d_in[5];
    const float* Whh = (const float*)d_in[6];
    const float* bih = (const float*)d_in[7];
    const float* bhh = (const float*)d_in[8];
    const float* Wp  = (const float*)d_in[9];
    const float* bp  = (const float*)d_in[10];
    float* out = (float*)d_out;

    (void)in_sizes; (void)n_in; (void)out_size;

    k_init<<<32, 256>>>(bih, bhh);
    k_deg_accum<<<(NEDGE + 255) / 256, 256>>>(ei, ew);
    k_deg_finish<<<4, 256>>>();
    k_norm_colcnt<<<(NEDGE + 255) / 256, 256>>>(ei, ew);
    k_scan<<<1, 1024>>>();
    k_scatter<<<(NEDGE + 255) / 256, 256>>>(ei);
    k_x0agg<<<(TSTEP * NNODE * CIN + 255) / 256, 256>>>(x, ei);
    k_vraw<<<(JDIM * NNODE) / 256, 256>>>(Wih, Wg, bg);
    dim3 gg(BATCH, JDIM / BN);
    k_gemm<<<gg, 256>>>(x);
    k_lstm<<<LBLK, 128>>>(Whh);
    k_proj<<<1, BATCH * NOUTD>>>(Wp, bp, out);
}

// round 6
// speedup vs baseline: 2.9321x; 1.9885x over previous
#include <cuda_runtime.h>
#include <cuda_bf16.h>
#include <math.h>
#include <stdint.h>

#define NNODE 1000
#define NEDGE 16000
#define BATCH 32
#define TSTEP 64
#define CIN   8
#define HGC   16
#define HL    256
#define NOUTD 24
#define KDIM  8000          // N*C
#define JDIM  1024          // 4*HL
#define WIHK  16000         // N*HG
#define KP    24000         // extended K: A'=[Ah|Ah|Al], B'=[Bh|Bl|Bh]
#define MROWS 2048
#define BKT   64
#define NCHUNK (KP / BKT)   // 375

typedef unsigned long long u64;

// ---------------- scratch (device globals; no allocation) ----------------
__device__ __align__(16) __nv_bfloat16 g_Abf[MROWS * KP];   // 98.3 MB
__device__ __align__(16) __nv_bfloat16 g_Bbf[JDIM * KP];    // 49.2 MB
__device__ __align__(16) float g_x0agg[TSTEP * KDIM];       // 2 MB
__device__ __align__(16) float g_gates[TSTEP * BATCH * JDIM]; // 8.4 MB
__device__ float g_biasfull[JDIM];
__device__ float g_deginv[NNODE];
__device__ float g_dis[NNODE];
__device__ float g_norm[NEDGE];
__device__ int   g_colcnt[NNODE + 1];
__device__ int   g_colptr[NNODE + 1];
__device__ int   g_cursor[NNODE];
__device__ int   g_ecol[NEDGE];
__device__ __align__(16) float g_hst[2][BATCH * HL];
__device__ int   g_bcnt;
__device__ int   g_bgen;

// ---------------- helpers ----------------
__device__ __forceinline__ uint32_t smem_u32(const void* p) {
    uint32_t a;
    asm("{ .reg .u64 t; cvta.to.shared.u64 t, %1; cvt.u32.u64 %0, t; }" : "=r"(a) : "l"(p));
    return a;
}
#define CP_ASYNC16(saddr, gptr) \
    asm volatile("cp.async.cg.shared.global [%0], [%1], 16;" :: "r"(saddr), "l"(gptr))
#define CP_COMMIT() asm volatile("cp.async.commit_group;")
#define CP_WAIT(n)  asm volatile("cp.async.wait_group %0;" :: "n"(n))

#define LDMX4(r0, r1, r2, r3, a) \
    asm volatile("ldmatrix.sync.aligned.m8n8.x4.shared.b16 {%0,%1,%2,%3}, [%4];" \
        : "=r"(r0), "=r"(r1), "=r"(r2), "=r"(r3) : "r"(a))

#define MMA16816(c, a, b0, b1) \
    asm volatile("mma.sync.aligned.m16n8k16.row.col.f32.bf16.bf16.f32 " \
        "{%0,%1,%2,%3},{%4,%5,%6,%7},{%8,%9},{%0,%1,%2,%3};" \
        : "+f"((c)[0]), "+f"((c)[1]), "+f"((c)[2]), "+f"((c)[3]) \
        : "r"((a)[0]), "r"((a)[1]), "r"((a)[2]), "r"((a)[3]), "r"(b0), "r"(b1))

// ---------------- f32x2 (LSTM) ----------------
__device__ __forceinline__ u64 pack2(float lo, float hi) {
    u64 r; asm("mov.b64 %0, {%1, %2};" : "=l"(r) : "f"(lo), "f"(hi)); return r;
}
__device__ __forceinline__ void unpack2(float& lo, float& hi, u64 v) {
    asm("mov.b64 {%0, %1}, %2;" : "=f"(lo), "=f"(hi) : "l"(v));
}
#define FFMA2(acc, a, w) asm("fma.rn.f32x2 %0, %1, %2, %0;" : "+l"(acc) : "l"(a), "l"(w))

// ---------------- small prep kernels ----------------
__global__ void k_init(const float* __restrict__ bih, const float* __restrict__ bhh) {
    int i = blockIdx.x * blockDim.x + threadIdx.x;
    if (i < NNODE) { g_deginv[i] = 1.0f; g_cursor[i] = 0; }
    if (i <= NNODE) g_colcnt[i] = 0;
    if (i < JDIM) g_biasfull[i] = bih[i] + bhh[i];
    if (i < BATCH * HL) g_hst[0][i] = 0.f;
    if (i == 0) { g_bcnt = 0; g_bgen = 0; }
}

__global__ void k_deg_accum(const int* __restrict__ ei, const float* __restrict__ ew) {
    int e = blockIdx.x * blockDim.x + threadIdx.x;
    if (e < NEDGE) atomicAdd(&g_deginv[ei[NEDGE + e]], ew[e]);
}

__global__ void k_deg_finish() {
    int n = blockIdx.x * blockDim.x + threadIdx.x;
    if (n < NNODE) {
        float d = g_deginv[n];
        g_deginv[n] = 1.0f / d;
        g_dis[n] = rsqrtf(d);
    }
}

__global__ void k_norm_colcnt(const int* __restrict__ ei, const float* __restrict__ ew) {
    int e = blockIdx.x * blockDim.x + threadIdx.x;
    if (e < NEDGE) {
        int r = ei[e], c = ei[NEDGE + e];
        g_norm[e] = g_dis[r] * ew[e] * g_dis[c];
        atomicAdd(&g_colcnt[c], 1);
    }
}

__global__ void k_scan() {
    __shared__ int s[1024];
    int tid = threadIdx.x;
    int c = (tid < NNODE) ? g_colcnt[tid] : 0;
    s[tid] = c;
    for (int off = 1; off < 1024; off <<= 1) {
        __syncthreads();
        int v = (tid >= off) ? s[tid - off] : 0;
        __syncthreads();
        s[tid] += v;
    }
    __syncthreads();
    if (tid < NNODE) {
        int ex = s[tid] - c;
        g_colptr[tid] = ex;
        g_cursor[tid] = ex;
    }
    if (tid == 1023) g_colptr[NNODE] = s[1023];
}

__global__ void k_scatter(const int* __restrict__ ei) {
    int e = blockIdx.x * blockDim.x + threadIdx.x;
    if (e < NEDGE) {
        int pos = atomicAdd(&g_cursor[ei[NEDGE + e]], 1);
        g_ecol[pos] = e;
    }
}

__global__ void k_x0agg(const float* __restrict__ x, const int* __restrict__ ei) {
    int idx = blockIdx.x * blockDim.x + threadIdx.x;
    int c = idx & 7;
    int tm = idx >> 3;
    int m = tm % NNODE;
    int t = tm / NNODE;
    const float* xb = x + (size_t)t * KDIM;
    float acc = g_deginv[m] * xb[m * CIN + c];
    int s = g_colptr[m], epos = g_colptr[m + 1];
    for (int p = s; p < epos; p++) {
        int e = g_ecol[p];
        int r = ei[e];
        acc = fmaf(g_norm[e], xb[r * CIN + c], acc);
    }
    g_x0agg[(size_t)t * KDIM + m * CIN + c] = acc;
}

// split A rows (batch0 rows come from x0agg) into bf16 hi/lo extended-K layout
__global__ void k_splitA(const float* __restrict__ x) {
    int idx = blockIdx.x * blockDim.x + threadIdx.x; // 0 .. 2048*2000-1
    if (idx >= MROWS * 2000) return;
    int r = idx / 2000, q = idx - r * 2000;
    const float* src = (r < 64) ? (g_x0agg + (size_t)r * KDIM) : (x + (size_t)r * KDIM);
    float4 v = *(const float4*)(src + q * 4);
    float vv[4] = {v.x, v.y, v.z, v.w};
    u64 hp, lp;
    __nv_bfloat16* hb = (__nv_bfloat16*)&hp;
    __nv_bfloat16* lb = (__nv_bfloat16*)&lp;
#pragma unroll
    for (int i = 0; i < 4; i++) {
        float f = vv[i];
        __nv_bfloat16 hi = __float2bfloat16(f);
        hb[i] = hi;
        lb[i] = __float2bfloat16(f - __bfloat162float(hi));
    }
    size_t base = (size_t)r * KP + q * 4;
    *(u64*)(g_Abf + base) = hp;
    *(u64*)(g_Abf + base + KDIM) = hp;
    *(u64*)(g_Abf + base + 2 * KDIM) = lp;
}

// V[j,n,c] = sum_h W_ih[j,n*16+h]*W_gcn[c,h] -> bf16 hi/lo into B'; fused bias partial
__global__ void k_vraw(const float* __restrict__ Wih, const float* __restrict__ Wg,
                       const float* __restrict__ bg) {
    __shared__ float wg[CIN * HGC];
    __shared__ float bgs[HGC];
    if (threadIdx.x < CIN * HGC) wg[threadIdx.x] = Wg[threadIdx.x];
    if (threadIdx.x < HGC) bgs[threadIdx.x] = bg[threadIdx.x];
    __syncthreads();
    int idx = blockIdx.x * blockDim.x + threadIdx.x;
    int j = idx / NNODE, n = idx % NNODE;
    float wih[HGC];
    const float4* p = (const float4*)(Wih + (size_t)j * WIHK + n * HGC);
#pragma unroll
    for (int q = 0; q < 4; q++) {
        float4 v = p[q];
        wih[q * 4 + 0] = v.x; wih[q * 4 + 1] = v.y; wih[q * 4 + 2] = v.z; wih[q * 4 + 3] = v.w;
    }
    uint4 hq, lq;
    __nv_bfloat16* hb = (__nv_bfloat16*)&hq;
    __nv_bfloat16* lb = (__nv_bfloat16*)&lq;
#pragma unroll
    for (int c = 0; c < CIN; c++) {
        float s = 0.f;
#pragma unroll
        for (int h = 0; h < HGC; h++) s = fmaf(wih[h], wg[c * HGC + h], s);
        __nv_bfloat16 hi = __float2bfloat16(s);
        hb[c] = hi;
        lb[c] = __float2bfloat16(s - __bfloat162float(hi));
    }
    size_t base = (size_t)j * KP + n * CIN;
    *(uint4*)(g_Bbf + base) = hq;
    *(uint4*)(g_Bbf + base + KDIM) = lq;
    *(uint4*)(g_Bbf + base + 2 * KDIM) = hq;
    float bpart = 0.f;
#pragma unroll
    for (int h = 0; h < HGC; h++) bpart = fmaf(wih[h], bgs[h], bpart);
    atomicAdd(&g_biasfull[j], bpart);
}

// ---------------- HMMA GEMM: 128x128 tile, K'=24000, mma.sync bf16 ----------------
#define SOFF_BIAS 0
#define SOFF_A 1024
#define SOFF_B (1024 + 32768)
#define GEMM_SMEM (1024 + 65536)

__global__ void __launch_bounds__(256) k_mma() {
    extern __shared__ __align__(1024) char smem[];
    const int tid = threadIdx.x, wid = tid >> 5, lane = tid & 31;
    const int bm = blockIdx.x, bn = blockIdx.y;
    uint32_t sb = smem_u32(smem);

    float* sbias = (float*)(smem + SOFF_BIAS);
    if (tid < 128) sbias[tid] = g_biasfull[bn * 128 + tid];

    const __nv_bfloat16* Ab = g_Abf + (size_t)bm * 128 * KP;
    const __nv_bfloat16* Bb = g_Bbf + (size_t)bn * 128 * KP;

    // per-thread cp.async coordinates (4 A + 4 B chunks of 16B per stage)
    int ld_r[4], ld_sw[4];
#pragma unroll
    for (int it = 0; it < 4; it++) {
        int idx = tid + it * 256;
        int r = idx >> 3, c16 = idx & 7;
        ld_r[it] = r;
        ld_sw[it] = r * 128 + ((c16 * 16) ^ ((r & 7) << 4));
    }

    // prologue: load chunk 0 into stage 0
#pragma unroll
    for (int it = 0; it < 4; it++) {
        CP_ASYNC16(sb + SOFF_A + ld_sw[it], Ab + (size_t)ld_r[it] * KP + (it * 0) + ( (tid + it*256) & 7) * 8);
    }
    // (re-issue properly below; the above line is replaced by the generic loader)
    // NOTE: to keep a single code path, we actually use the lambda-style macro:
#define LOAD_STAGE(stage, kb)                                                     \
    do {                                                                          \
        char* _sA = smem + SOFF_A + (stage) * 16384;                              \
        char* _sB = smem + SOFF_B + (stage) * 16384;                              \
        _Pragma("unroll")                                                         \
        for (int _it = 0; _it < 4; _it++) {                                       \
            int _idx = tid + _it * 256;                                           \
            int _c16 = _idx & 7;                                                  \
            CP_ASYNC16(smem_u32(_sA + ld_sw[_it]),                                \
                       Ab + (size_t)ld_r[_it] * KP + (kb) + _c16 * 8);            \
            CP_ASYNC16(smem_u32(_sB + ld_sw[_it]),                                \
                       Bb + (size_t)ld_r[_it] * KP + (kb) + _c16 * 8);            \
        }                                                                         \
        CP_COMMIT();                                                              \
    } while (0)

    // warp tile: wm in {0,1} (64 rows), wn in {0..3} (32 cols)
    const int wm = wid & 1, wn = wid >> 1;
    // A ldmatrix lane mapping: row = base + (lane&15), 16B-chunk = lane>>4
    const int a_rl = lane & 15, a_ck = lane >> 4;
    // B ldmatrix lane mapping: n = base + (lane&7) + ((lane>>4)<<3), chunk = (lane>>3)&1
    const int b_nl = (lane & 7) + ((lane >> 4) << 3), b_ck = (lane >> 3) & 1;

    float acc[4][4][4];
#pragma unroll
    for (int i = 0; i < 4; i++)
#pragma unroll
        for (int j = 0; j < 4; j++)
#pragma unroll
            for (int q = 0; q < 4; q++) acc[i][j][q] = 0.f;

    LOAD_STAGE(0, 0);

    for (int c = 0; c < NCHUNK; c++) {
        int s = c & 1;
        if (c + 1 < NCHUNK) {
            LOAD_STAGE(1 - s, (c + 1) * BKT);
            CP_WAIT(1);
        } else {
            CP_WAIT(0);
        }
        __syncthreads();

        uint32_t aBase = sb + SOFF_A + s * 16384;
        uint32_t bBase = sb + SOFF_B + s * 16384;
#pragma unroll
        for (int ks = 0; ks < 4; ks++) {
            uint32_t af[4][4];
#pragma unroll
            for (int fm = 0; fm < 4; fm++) {
                int r = wm * 64 + fm * 16 + a_rl;
                uint32_t addr = aBase + r * 128 + ((((ks * 2 + a_ck) * 16)) ^ ((r & 7) << 4));
                LDMX4(af[fm][0], af[fm][1], af[fm][2], af[fm][3], addr);
            }
            uint32_t bf[2][4];
#pragma unroll
            for (int bi = 0; bi < 2; bi++) {
                int n = wn * 32 + bi * 16 + b_nl;
                uint32_t addr = bBase + n * 128 + ((((ks * 2 + b_ck) * 16)) ^ ((n & 7) << 4));
                LDMX4(bf[bi][0], bf[bi][1], bf[bi][2], bf[bi][3], addr);
            }
#pragma unroll
            for (int fm = 0; fm < 4; fm++)
#pragma unroll
                for (int fn = 0; fn < 4; fn++) {
                    uint32_t b0 = bf[fn >> 1][(fn & 1) * 2];
                    uint32_t b1 = bf[fn >> 1][(fn & 1) * 2 + 1];
                    MMA16816(acc[fm][fn], af[fm], b0, b1);
                }
        }
        __syncthreads();
    }

    // epilogue: write gates with bias
    const int gid = lane >> 2, tg = lane & 3;
#pragma unroll
    for (int fm = 0; fm < 4; fm++) {
        int m0 = bm * 128 + wm * 64 + fm * 16 + gid;
        int b0i = m0 >> 6, t0 = m0 & 63;
        int m1 = m0 + 8;
        int b1i = m1 >> 6, t1 = m1 & 63;
        float* g0 = g_gates + (size_t)t0 * (BATCH * JDIM) + b0i * JDIM + bn * 128;
        float* g1 = g_gates + (size_t)t1 * (BATCH * JDIM) + b1i * JDIM + bn * 128;
#pragma unroll
        for (int fn = 0; fn < 4; fn++) {
            int jl = wn * 32 + fn * 8 + tg * 2;
            float bx = sbias[jl], by = sbias[jl + 1];
            float2 v0 = make_float2(acc[fm][fn][0] + bx, acc[fm][fn][1] + by);
            float2 v1 = make_float2(acc[fm][fn][2] + bx, acc[fm][fn][3] + by);
            *(float2*)(g0 + jl) = v0;
            *(float2*)(g1 + jl) = v1;
        }
    }
#undef LOAD_STAGE
}

// ---------------- persistent LSTM ----------------
__device__ __forceinline__ float sigf(float x) { return 1.0f / (1.0f + expf(-x)); }

#define LBLK 64
__global__ void __launch_bounds__(128) k_lstm(const float* __restrict__ Whh) {
    __shared__ __align__(16) float Wsm[16][HL];
    __shared__ u64 hp[HL / 2][33];
    int tid = threadIdx.x;
    int u0 = blockIdx.x * 4;
    for (int i = tid; i < 16 * HL; i += 128) {
        int r = i >> 8, k = i & 255;
        int jj = r >> 2, g = r & 3;
        Wsm[r][k] = Whh[(size_t)(g * HL + u0 + jj) * HL + k];
    }
    int b = tid & 31, jj = tid >> 5;
    int u = u0 + jj;
    float creg = 0.f;
    int mygen = 0;

    for (int t = 0; t < TSTEP; t++) {
        int p = t & 1;
        __syncthreads();
        const float* hsrc = g_hst[p];
        for (int i = tid; i < BATCH * (HL / 2); i += 128) {
            int k2 = i & 127, bb = i >> 7;
            float2 hv = *(const float2*)(hsrc + bb * HL + k2 * 2);
            hp[k2][bb] = pack2(hv.x, hv.y);
        }
        __syncthreads();
        u64 acc[4] = {0ull, 0ull, 0ull, 0ull};
#pragma unroll 4
        for (int k2 = 0; k2 < HL / 2; k2++) {
            u64 h2 = hp[k2][b];
#pragma unroll
            for (int g = 0; g < 4; g++) {
                u64 w2 = *(const u64*)&Wsm[jj * 4 + g][k2 * 2];
                FFMA2(acc[g], h2, w2);
            }
        }
        const float* gin = g_gates + (size_t)t * (BATCH * JDIM) + b * JDIM;
        float gv[4];
#pragma unroll
        for (int g = 0; g < 4; g++) {
            float lo, hi; unpack2(lo, hi, acc[g]);
            gv[g] = lo + hi + __ldg(gin + g * HL + u);
        }
        float cn = sigf(gv[1]) * creg + sigf(gv[0]) * tanhf(gv[2]);
        float hn = sigf(gv[3]) * tanhf(cn);
        creg = cn;
        g_hst[1 - p][b * HL + u] = hn;
        __threadfence();
        __syncthreads();
        if (tid == 0) {
            int old = atomicAdd(&g_bcnt, 1);
            if (old == LBLK - 1) {
                atomicExch(&g_bcnt, 0);
                __threadfence();
                ((volatile int*)&g_bgen)[0] = mygen + 1;
            } else {
                while (((volatile int*)&g_bgen)[0] <= mygen) { }
            }
        }
        __syncthreads();
        __threadfence();
        mygen++;
    }
}

__global__ void k_proj(const float* __restrict__ Wp, const float* __restrict__ bp,
                       float* __restrict__ out) {
    int tid = threadIdx.x;
    if (tid >= BATCH * NOUTD) return;
    int b = tid / NOUTD, o = tid % NOUTD;
    const float* h = g_hst[0] + b * HL;
    const float* w = Wp + o * HL;
    float s = 0.f;
#pragma unroll 8
    for (int k = 0; k < HL; k++) s = fmaf(h[k], w[k], s);
    out[b * NOUTD + o] = s + bp[o];
}

// ---------------- launch ----------------
extern "C" void kernel_launch(void* const* d_in, const int* in_sizes, int n_in,
                              void* d_out, int out_size) {
    const float* x   = (const float*)d_in[0];
    const int*   ei  = (const int*)d_in[1];
    const float* ew  = (const float*)d_in[2];
    const float* Wg  = (const float*)d_in[3];
    const float* bg  = (const float*)d_in[4];
    const float* Wih = (const float*)d_in[5];
    const float* Whh = (const float*)d_in[6];
    const float* bih = (const float*)d_in[7];
    const float* bhh = (const float*)d_in[8];
    const float* Wp  = (const float*)d_in[9];
    const float* bp  = (const float*)d_in[10];
    float* out = (float*)d_out;

    (void)in_sizes; (void)n_in; (void)out_size;

    cudaFuncSetAttribute(k_mma, cudaFuncAttributeMaxDynamicSharedMemorySize, GEMM_SMEM);

    k_init<<<32, 256>>>(bih, bhh);
    k_deg_accum<<<(NEDGE + 255) / 256, 256>>>(ei, ew);
    k_deg_finish<<<4, 256>>>();
    k_norm_colcnt<<<(NEDGE + 255) / 256, 256>>>(ei, ew);
    k_scan<<<1, 1024>>>();
    k_scatter<<<(NEDGE + 255) / 256, 256>>>(ei);
    k_x0agg<<<(TSTEP * NNODE * CIN + 255) / 256, 256>>>(x, ei);
    k_splitA<<<(MROWS * 2000 + 255) / 256, 256>>>(x);
    k_vraw<<<(JDIM * NNODE) / 256, 256>>>(Wih, Wg, bg);
    k_mma<<<dim3(16, 8), 256, GEMM_SMEM>>>();
    k_lstm<<<LBLK, 128>>>(Whh);
    k_proj<<<1, BATCH * NOUTD>>>(Wp, bp, out);
}